// round 5
// baseline (speedup 1.0000x reference)
#include <cuda_runtime.h>
#include <math.h>

#define AHW    43264          // 208*208
#define Q4     10816          // AHW/4
#define NB4    54080          // 5*Q4 conf float4s
#define WGRID  208
#define NCLS   80
#define SHIFT  17
#define HB     16384          // buckets over p4 float bits >> 17
#define CAP    2048
#define KTOP   1024
#define GRID   53

__device__ __align__(16) unsigned g_hist[HB];
__device__ unsigned long long  g_keys[CAP];
__device__ unsigned long long  g_rank[KTOP];
__device__ int                 g_count;
__device__ unsigned            g_sync[8];
__device__ float4              g_tb[KTOP];
__device__ float               g_tconf[KTOP];
__device__ int                 g_tcls[KTOP];
__device__ unsigned            g_keep0[32];
__device__ unsigned            g_rowAny[32];
__device__ unsigned            g_sup[KTOP * 32];

extern __shared__ unsigned char dynsmem[];

// grid-wide spin barrier (all GRID blocks resident: 148KB smem -> 1 block/SM, 53 <= 148 SMs)
__device__ __forceinline__ void gsync(int idx) {
    __syncthreads();
    if (threadIdx.x == 0) {
        __threadfence();
        unsigned* c = &g_sync[idx];
        atomicAdd(c, 1u);
        while (*(volatile unsigned*)c < GRID) __nanosleep(32);
        __threadfence();
    }
    __syncthreads();
}

__global__ void __launch_bounds__(1024) yolo_kernel(const float* __restrict__ x,
                                                    const float* __restrict__ anchors,
                                                    float* __restrict__ out) {
    // dynamic smem layout (phases disjoint in time per block):
    unsigned long long* kc = (unsigned long long*)dynsmem;            // P2: 16 KB key cache
    unsigned* rows = (unsigned*)dynsmem;                              // P5: 128 KB
    float4*   sb   = (float4*)(dynsmem + 131072);                     // P4: 16 KB
    int*      scl  = (int*)(dynsmem + 131072 + 16384);                // P4: 4 KB

    __shared__ unsigned suf[1024];
    __shared__ int s_c;
    __shared__ unsigned s_T;
    __shared__ unsigned s_valid;
    __shared__ bool s_last;
    __shared__ unsigned s_keep[32];
    __shared__ unsigned s_any[32];

    int tid  = threadIdx.x;
    int wid  = tid >> 5;
    int lane = tid & 31;
    int bid  = blockIdx.x;
    int t    = bid * 1024 + tid;

    // ================= P0: conf histogram (float4 stays in regs) + zero g_rank
    float4 p = make_float4(-1.f, -1.f, -1.f, -1.f);
    int a = 0, q = 0;
    if (t < NB4) {
        a = t / Q4;
        q = t - a * Q4;
        p = __ldg((const float4*)(x + (size_t)(a * 85 + 4) * AHW) + q);
        if (p.x > 0.f) atomicAdd(&g_hist[__float_as_uint(p.x) >> SHIFT], 1u);
        if (p.y > 0.f) atomicAdd(&g_hist[__float_as_uint(p.y) >> SHIFT], 1u);
        if (p.z > 0.f) atomicAdd(&g_hist[__float_as_uint(p.z) >> SHIFT], 1u);
        if (p.w > 0.f) atomicAdd(&g_hist[__float_as_uint(p.w) >> SHIFT], 1u);
    }
    if (bid == GRID - 1) g_rank[tid] = 0ull;

    gsync(0);

    // ================= P1: per-block threshold (parallel suffix scan) + compact
    {
        const uint4* h4 = (const uint4*)g_hist;
        uint4 a0 = h4[tid * 4 + 0], a1 = h4[tid * 4 + 1], a2 = h4[tid * 4 + 2], a3 = h4[tid * 4 + 3];
        suf[tid] = a0.x + a0.y + a0.z + a0.w + a1.x + a1.y + a1.z + a1.w
                 + a2.x + a2.y + a2.z + a2.w + a3.x + a3.y + a3.z + a3.w;
        if (tid == 0) s_c = -1;
        __syncthreads();
        for (int d = 1; d < 1024; d <<= 1) {
            unsigned v = (tid + d < 1024) ? suf[tid + d] : 0u;
            __syncthreads();
            suf[tid] += v;
            __syncthreads();
        }
        unsigned mine = suf[tid];
        unsigned nxt = (tid < 1023) ? suf[tid + 1] : 0u;
        if (mine >= KTOP && nxt < KTOP) s_c = tid;
        __syncthreads();
        if (tid == 0) {
            int c = s_c;
            if (c < 0) s_T = 0u;
            else {
                unsigned acc = (c < 1023) ? suf[c + 1] : 0u;
                int T = c * 16;
                for (int b = 15; b >= 0; b--) {
                    acc += g_hist[c * 16 + b];
                    if (acc >= KTOP) { T = c * 16 + b; break; }
                }
                T -= 2;                                  // tie-safety margin
                if (T < 0) T = 0;
                s_T = (unsigned)T;
            }
        }
        __syncthreads();
        unsigned T = s_T;

        if (t < NB4) {
            float pv[4] = {p.x, p.y, p.z, p.w};
#pragma unroll
            for (int c = 0; c < 4; c++) {
                float v = pv[c];
                if (v > 0.f && (__float_as_uint(v) >> SHIFT) >= T) {
                    int pos = atomicAdd(&g_count, 1);
                    if (pos < CAP) {
                        unsigned idx = (unsigned)(a * AHW + q * 4 + c);
                        double e = exp(-(double)v);
                        float conf = (float)(1.0 / (1.0 + e));
                        g_keys[pos] = ((unsigned long long)__float_as_uint(conf) << 32)
                                      | (unsigned)(~idx);
                    }
                }
            }
        }
    }

    gsync(1);

    // ================= P2: rank-by-counting scatter (blocks 0,1) | hist zero (2..5) | count reset (6)
    if (bid < 2) {
        kc[tid]        = __ldcg(&g_keys[tid]);
        kc[tid + 1024] = __ldcg(&g_keys[tid + 1024]);
        __syncthreads();
        int c = bid * 1024 + tid;
        unsigned long long my = kc[c];
        if (my != 0ull) {
            int rk = 0;
#pragma unroll 8
            for (int j = 0; j < CAP; j++) rk += (kc[j] > my) ? 1 : 0;
            if (rk < KTOP) g_rank[rk] = my;
        }
    } else if (bid >= 2 && bid < 6) {
        ((uint4*)g_hist)[(bid - 2) * 1024 + tid] = make_uint4(0u, 0u, 0u, 0u);
    } else if (bid == 6 && tid == 0) {
        g_count = 0;
    }

    gsync(2);

    // ================= P3: warp-per-rank gather-decode (blocks 0..31) | g_keys zero (32)
    if (bid < 32) {
        if (tid == 0) s_valid = 0u;
        __syncthreads();
        int r = bid * 32 + wid;
        unsigned long long key = 0ull;
        if (lane == 0) key = __ldcg(&g_rank[r]);
        key = __shfl_sync(0xffffffffu, key, 0);

        float4 b4 = make_float4(0.f, 0.f, 0.f, 0.f);
        int cl = 0; float conf = 0.f;
        if (key != 0ull) {
            unsigned idx = ~(unsigned)(key & 0xFFFFFFFFull);
            conf = __uint_as_float((unsigned)(key >> 32));
            int aa = idx / AHW;
            int s = idx - aa * AHW;
            const float* px = x + (size_t)(aa * 85) * AHW + s;
            const float* pc = px + 5 * (size_t)AHW;
            float bv = -3.4e38f; int bi = NCLS;
#pragma unroll
            for (int m = 0; m < 3; m++) {
                int k = lane + 32 * m;
                if (k < NCLS) {
                    float v = __ldg(pc + (size_t)k * AHW);
                    if (v > bv || (v == bv && k < bi)) { bv = v; bi = k; }
                }
            }
#pragma unroll
            for (int off = 16; off > 0; off >>= 1) {
                float ov = __shfl_xor_sync(0xffffffffu, bv, off);
                int   oi = __shfl_xor_sync(0xffffffffu, bi, off);
                if (ov > bv || (ov == bv && oi < bi)) { bv = ov; bi = oi; }
            }
            cl = bi;
            if (lane == 0) {
                int h = s / WGRID;
                int w = s - h * WGRID;
                float p0 = __ldg(px);
                float p1 = __ldg(px + AHW);
                float p2 = __ldg(px + 2 * (size_t)AHW);
                float p3 = __ldg(px + 3 * (size_t)AHW);
                float aw = __ldg(&anchors[a * 2 + 0 + (aa - a) * 2]);  // = anchors[aa*2]
                float ah = __ldg(&anchors[aa * 2 + 1]);
                aw = __ldg(&anchors[aa * 2]);
                float bx = (1.f / (1.f + expf(-p0)) + (float)w) * 32.f;
                float by = (1.f / (1.f + expf(-p1)) + (float)h) * 32.f;
                b4 = make_float4(bx, by, expf(p2) * aw * 32.f, expf(p3) * ah * 32.f);
            }
        }
        if (lane == 0) {
            g_tb[r]    = b4;
            g_tcls[r]  = cl;
            g_tconf[r] = conf;
            if (key != 0ull) atomicOr(&s_valid, 1u << wid);
        }
        __syncthreads();
        if (tid == 0) g_keep0[bid] = s_valid;
    } else if (bid == 32) {
        g_keys[tid] = 0ull;
        g_keys[tid + 1024] = 0ull;
    }

    gsync(3);

    // ================= P4: suppression matrix, 32 rows/block (blocks 0..31)
    if (bid < 32) {
        sb[tid]  = __ldcg((const float4*)&g_tb[tid]);
        scl[tid] = __ldcg(&g_tcls[tid]);
        __shared__ unsigned s_blockAny;
        if (tid == 0) s_blockAny = 0u;
        __syncthreads();

        int i = bid * 32 + wid;
        float4 bi = sb[i];
        int   cli = scl[i];
        float x1min = (bi.x - bi.z) * 0.5f, y1min = (bi.y - bi.w) * 0.5f;
        float x1max = (bi.x + bi.z) * 0.5f, y1max = (bi.y + bi.w) * 0.5f;
        float a1 = fabsf((x1max - x1min) * (y1max - y1min));

        unsigned anyw = 0u;
#pragma unroll 4
        for (int c = 0; c < 32; c++) {
            int jj = c * 32 + lane;
            float4 bj = sb[jj];
            bool sup = false;
            if (jj > i && scl[jj] == cli) {
                float x2min = (bj.x - bj.z) * 0.5f, y2min = (bj.y - bj.w) * 0.5f;
                float x2max = (bj.x + bj.z) * 0.5f, y2max = (bj.y + bj.w) * 0.5f;
                float iw = fmaxf(fminf(x1max, x2max) - fmaxf(x1min, x2min), 0.f);
                float ih = fmaxf(fminf(y1max, y2max) - fmaxf(y1min, y2min), 0.f);
                float inter = iw * ih;
                float a2 = fabsf((x2max - x2min) * (y2max - y2min));
                float iou = inter / (a1 + a2 - inter + 1e-6f);
                sup = (iou >= 0.5f);
            }
            unsigned wmask = __ballot_sync(0xffffffffu, sup);
            if (lane == 0) g_sup[i * 32 + c] = wmask;
            anyw |= wmask;
        }
        if (lane == 0 && anyw) atomicOr(&s_blockAny, 1u << wid);
        __syncthreads();
        if (tid == 0) g_rowAny[bid] = s_blockAny;
    }

    // ================= final sync: last-arriving block does the greedy sweep
    __syncthreads();
    if (tid == 0) {
        __threadfence();
        s_last = (atomicAdd(&g_sync[4], 1u) == GRID - 1);
    }
    __syncthreads();
    if (!s_last) return;
    __threadfence();

    // ---- P5: cache active suppression rows in shared, sweep, output, reset
    if (tid < 32) s_any[tid] = __ldcg(&g_rowAny[tid]);
    __syncthreads();
    for (int i = wid; i < KTOP; i += 32) {
        if ((s_any[i >> 5] >> (i & 31)) & 1u)
            rows[i * 32 + lane] = __ldcg(&g_sup[i * 32 + lane]);
    }
    __syncthreads();

    if (tid < 32) {
        unsigned keepw = __ldcg(&g_keep0[tid]);
        unsigned anyv  = s_any[tid];
        for (int ww = 0; ww < 32; ww++) {
            unsigned aw = __shfl_sync(0xffffffffu, anyv,  ww);
            unsigned kw = __shfl_sync(0xffffffffu, keepw, ww);
            unsigned act = kw & aw;
            while (act) {
                int b = __ffs(act) - 1;
                keepw &= ~rows[(ww * 32 + b) * 32 + tid];
                kw = __shfl_sync(0xffffffffu, keepw, ww);
                act = kw & aw & (0xFFFFFFFEu << b);
            }
        }
        s_keep[tid] = keepw;
    }
    __syncthreads();

    {
        bool k = (s_keep[tid >> 5] >> (tid & 31)) & 1u;
        float4 b  = __ldcg((const float4*)&g_tb[tid]);
        float cf  = __ldcg(&g_tconf[tid]);
        int   cl  = __ldcg(&g_tcls[tid]);
        float* o = out + (size_t)tid * 6;
        if (k) {
            o[0] = b.x; o[1] = b.y; o[2] = b.z; o[3] = b.w;
            o[4] = cf;  o[5] = (float)cl;
        } else {
            o[0] = 0.f; o[1] = 0.f; o[2] = 0.f; o[3] = 0.f; o[4] = 0.f; o[5] = 0.f;
        }
    }
    if (tid < 8) g_sync[tid] = 0u;
}

// ---------------------------------------------------------------- launch
extern "C" void kernel_launch(void* const* d_in, const int* in_sizes, int n_in,
                              void* d_out, int out_size) {
    const float* x       = (const float*)d_in[0];
    const float* anchors = (const float*)d_in[1];
    float* out = (float*)d_out;

    static bool s_attr = false;
    const int SMEM = 131072 + 16384 + 4096;   // 148 KB
    if (!s_attr) {
        cudaFuncSetAttribute(yolo_kernel, cudaFuncAttributeMaxDynamicSharedMemorySize, SMEM);
        s_attr = true;
    }

    yolo_kernel<<<GRID, 1024, SMEM>>>(x, anchors, out);
}